// round 14
// baseline (speedup 1.0000x reference)
#include <cuda_runtime.h>
#include <cuda_fp16.h>

#define NN 100000
#define EE 1600000
#define GG 1000
#define BN_EPS 1e-5f
#define SCAN_NB 98   // ceil(NN/1024)
#define FULL 0xffffffffu

// ---------------- device scratch ----------------
__device__ int     g_is64;
__device__ int     g_cnt[NN];          // zeroed by k_scan after use
__device__ int     g_fill[NN];
__device__ int     g_rowptr[NN + 1];
__device__ int     g_col[EE];
__device__ float   g_dinv[NN];
__device__ __half2 g_xsh[NN * 2];      // x pre-scaled by dinv, packed fp16
__device__ float   g_bufA[NN * 64];
__device__ float   g_bufB[NN * 64];
__device__ __half2 g_h16A[NN * 32];    // prescaled by dinv_u
__device__ __half2 g_h16B[NN * 32];
__device__ unsigned long long g_scan_pub[SCAN_NB];
__device__ int     g_startg[GG + 1];
__device__ float   g_W0f[3 * 64];
__device__ float   g_b0f[64];
__device__ float   g_Wf[2][64 * 64];
__device__ float   g_bf[2][64];

__device__ __forceinline__ int ld_idx(const void* p, long i, int is64) {
    if (is64) return (int)((const long long*)p)[i];
    return ((const int*)p)[i];
}

#define PACK2(dst, lo, hi) asm("mov.b64 %0, {%1, %2};" : "=l"(dst) : "f"(lo), "f"(hi))
#define UNPACK2(lo, hi, src) asm("mov.b64 {%0, %1}, %2;" : "=f"(lo), "=f"(hi) : "l"(src))
#define FMA2(acc, a, b) asm("fma.rn.f32x2 %0, %1, %2, %0;" : "+l"(acc) : "l"(a), "l"(b))

// ---------------- prep (2 blocks) ----------------
__global__ void k_prep(const void* ei,
                       const float* __restrict__ W0, const float* __restrict__ b0,
                       const float* __restrict__ Wh, const float* __restrict__ bh,
                       const float* __restrict__ gam, const float* __restrict__ bet,
                       const float* __restrict__ mea, const float* __restrict__ var) {
    if (blockIdx.x == 0) {
        __shared__ int sh_any;
        if (threadIdx.x == 0) sh_any = 0;
        __syncthreads();
        long stride = EE / 256;
        long e = (long)threadIdx.x * stride + 1;
        const int* w = (const int*)ei;
        if (w[2 * e + 1] != 0) sh_any = 1;
        __syncthreads();
        if (threadIdx.x == 0) g_is64 = (sh_any == 0) ? 1 : 0;
    } else {
        for (int t = threadIdx.x; t < 3 * 64; t += 256) {
            int c = t % 64;
            g_W0f[t] = W0[t] * (gam[c] * rsqrtf(var[c] + BN_EPS));
        }
        for (int t = threadIdx.x; t < 64; t += 256) {
            float sc = gam[t] * rsqrtf(var[t] + BN_EPS);
            g_b0f[t] = (b0[t] - mea[t]) * sc + bet[t];
        }
        for (int l = 0; l < 2; ++l) {
            const float* G = gam + 64 * (l + 1);
            const float* B = bet + 64 * (l + 1);
            const float* M = mea + 64 * (l + 1);
            const float* V = var + 64 * (l + 1);
            for (int t = threadIdx.x; t < 64 * 64; t += 256) {
                int c = t % 64;
                g_Wf[l][t] = Wh[l * 4096 + t] * (G[c] * rsqrtf(V[c] + BN_EPS));
            }
            for (int t = threadIdx.x; t < 64; t += 256) {
                float sc = G[t] * rsqrtf(V[t] + BN_EPS);
                g_bf[l][t] = (bh[l * 64 + t] - M[t]) * sc + B[t];
            }
        }
    }
}

// ---------------- count + bounds ----------------
#define NB_E2 ((EE + 511) / 512)
#define NB_N  ((NN + 255) / 256)

__global__ void k_count_bounds(const void* ei, const void* batch) {
    int is64 = g_is64;
    if (blockIdx.x < NB_E2) {
        int e = (blockIdx.x * 256 + threadIdx.x) * 2;
        if (e >= EE) return;
        int d0, d1;
        if (is64) {
            longlong2 a = *(const longlong2*)((const long long*)ei + EE + e);
            d0 = (int)a.x; d1 = (int)a.y;
        } else {
            int2 a = *(const int2*)((const int*)ei + EE + e);
            d0 = a.x; d1 = a.y;
        }
        atomicAdd(&g_cnt[d0], 1);
        atomicAdd(&g_cnt[d1], 1);
    } else {
        int v = (blockIdx.x - NB_E2) * 256 + threadIdx.x;
        if (v >= NN) return;
        int b = ld_idx(batch, v, is64);
        if (v == 0) {
            for (int g = 0; g <= b; ++g) g_startg[g] = 0;
        } else {
            int pb = ld_idx(batch, v - 1, is64);
            for (int g = pb + 1; g <= b; ++g) g_startg[g] = v;
        }
        if (v == NN - 1) {
            for (int g = b + 1; g <= GG; ++g) g_startg[g] = NN;
        }
    }
}

// ---------------- single-pass scan, warp-parallel lookback ----------------
__global__ void k_scan(const float* __restrict__ x) {
    __shared__ int swarp[32];
    __shared__ int s_prev;
    int t = threadIdx.x, b = blockIdx.x;
    int i = b * 1024 + t;
    int v = (i < NN) ? g_cnt[i] : 0;
    int lane = t & 31, w = t >> 5;

    int xx = v;
#pragma unroll
    for (int off = 1; off < 32; off <<= 1) {
        int y = __shfl_up_sync(FULL, xx, off);
        if (lane >= off) xx += y;
    }
    if (lane == 31) swarp[w] = xx;
    __syncthreads();
    if (t < 32) {
        int z = swarp[t];
#pragma unroll
        for (int off = 1; off < 32; off <<= 1) {
            int y = __shfl_up_sync(FULL, z, off);
            if (t >= off) z += y;
        }
        swarp[t] = z;
    }
    __syncthreads();
    int incl = xx + (w > 0 ? swarp[w - 1] : 0);
    int agg = swarp[31];
    __syncthreads();

    if (b == 0) {
        if (t == 0) {
            atomicExch(&g_scan_pub[0], (2ULL << 32) | (unsigned)agg);
            s_prev = 0;
        }
    } else {
        if (t == 0) atomicExch(&g_scan_pub[b], (1ULL << 32) | (unsigned)agg);
        if (t < 32) {
            int run = 0;
            int end = b;
            while (true) {
                int j = end - 32 + lane;
                unsigned long long p;
                unsigned st;
                if (j >= 0) {
                    p = atomicAdd(&g_scan_pub[j], 0ULL);
                    st = (unsigned)(p >> 32);
                } else { p = 0; st = 2u; }
                unsigned inval = __ballot_sync(FULL, st == 0u);
                if (inval) continue;
                unsigned pref = __ballot_sync(FULL, st == 2u);
                int val;
                if (pref) {
                    int hi = 31 - __clz(pref);
                    val = (lane >= hi) ? (int)(unsigned)p : 0;
                } else {
                    val = (int)(unsigned)p;
                }
#pragma unroll
                for (int o = 16; o > 0; o >>= 1) val += __shfl_xor_sync(FULL, val, o);
                run += val;
                if (pref) break;
                end -= 32;
            }
            if (lane == 0) {
                atomicExch(&g_scan_pub[b], (2ULL << 32) | (unsigned)(run + agg));
                s_prev = run;
            }
        }
    }
    __syncthreads();
    int ex = s_prev + incl - v;
    if (i < NN) {
        g_rowptr[i] = ex;
        g_fill[i] = ex;
        float dv = rsqrtf((float)v + 1.0f);
        g_dinv[i] = dv;
        g_cnt[i] = 0;
        g_xsh[i * 2 + 0] = __floats2half2_rn(x[i * 3 + 0] * dv, x[i * 3 + 1] * dv);
        g_xsh[i * 2 + 1] = __floats2half2_rn(x[i * 3 + 2] * dv, 0.f);
    }
    if (b == 0 && t == 0) g_rowptr[NN] = EE;
}

// ---------------- fill ----------------
__global__ void k_fill(const void* ei) {
    if (blockIdx.x == 0 && threadIdx.x < SCAN_NB)
        g_scan_pub[threadIdx.x] = 0ULL;
    int is64 = g_is64;
    int e = (blockIdx.x * 256 + threadIdx.x) * 2;
    if (e >= EE) return;
    int s0, s1, d0, d1;
    if (is64) {
        longlong2 sa = *(const longlong2*)((const long long*)ei + e);
        longlong2 da = *(const longlong2*)((const long long*)ei + EE + e);
        s0 = (int)sa.x; s1 = (int)sa.y;
        d0 = (int)da.x; d1 = (int)da.y;
    } else {
        int2 sa = *(const int2*)((const int*)ei + e);
        int2 da = *(const int2*)((const int*)ei + EE + e);
        s0 = sa.x; s1 = sa.y;
        d0 = da.x; d1 = da.y;
    }
    g_col[atomicAdd(&g_fill[d0], 1)] = s0;
    g_col[atomicAdd(&g_fill[d1], 1)] = s1;
}

// ---------------- layer 0: broadcast-edge gather (all lanes same row; x4 ILP) ----------------
__device__ __forceinline__ void xs_acc(int u, float& a0, float& a1, float& a2) {
    uint2 pk = __ldg((const uint2*)&g_xsh[u * 2]);
    __half2 p0 = *reinterpret_cast<__half2*>(&pk.x);
    __half2 p1 = *reinterpret_cast<__half2*>(&pk.y);
    float2 f0 = __half22float2(p0);
    a0 += f0.x;
    a1 += f0.y;
    a2 += __low2float(p1);
}

__global__ void k_layer0() {
    int warp = threadIdx.x >> 5, lane = threadIdx.x & 31;
    int v = blockIdx.x * 8 + warp;
    if (v >= NN) return;
    int r0 = g_rowptr[v], r1 = g_rowptr[v + 1];
    // all lanes walk the same edges (broadcast loads: 1 sector each)
    float a0 = 0.f, a1 = 0.f, a2 = 0.f;
    float b0 = 0.f, b1 = 0.f, b2 = 0.f;
    float c0 = 0.f, c1 = 0.f, c2 = 0.f;
    float d0 = 0.f, d1 = 0.f, d2 = 0.f;
    int e = r0;
    for (; e + 4 <= r1; e += 4) {
        int u0 = __ldg(&g_col[e]);
        int u1 = __ldg(&g_col[e + 1]);
        int u2 = __ldg(&g_col[e + 2]);
        int u3 = __ldg(&g_col[e + 3]);
        xs_acc(u0, a0, a1, a2);
        xs_acc(u1, b0, b1, b2);
        xs_acc(u2, c0, c1, c2);
        xs_acc(u3, d0, d1, d2);
    }
    for (; e < r1; ++e) {
        int u = __ldg(&g_col[e]);
        xs_acc(u, a0, a1, a2);
    }
    a0 += (b0 + c0) + d0;
    a1 += (b1 + c1) + d1;
    a2 += (b2 + c2) + d2;
    float dv = g_dinv[v];
    float s0 = 0.f, s1 = 0.f, s2 = 0.f;
    xs_acc(v, s0, s1, s2);
    a0 = dv * (a0 + s0);
    a1 = dv * (a1 + s1);
    a2 = dv * (a2 + s2);
    int c = 2 * lane;
    float o0 = a0 * g_W0f[c]     + a1 * g_W0f[64 + c]     + a2 * g_W0f[128 + c]     + g_b0f[c];
    float o1 = a0 * g_W0f[c + 1] + a1 * g_W0f[64 + c + 1] + a2 * g_W0f[128 + c + 1] + g_b0f[c + 1];
    o0 = fmaxf(o0, 0.f);
    o1 = fmaxf(o1, 0.f);
    ((float2*)g_bufA)[v * 32 + lane] = make_float2(o0, o1);
    g_h16A[v * 32 + lane] = __floats2half2_rn(o0 * dv, o1 * dv);
}

// ---------------- layers 1,2: 4 nodes/warp; x4 gather ILP; shared-weight packed-FMA matmul (R12 exact) ----------------
__global__ void k_layer(int sel, int write16, int lidx) {
    __shared__ float2 sW[64 * 32];
    const float2* W2 = (const float2*)g_Wf[lidx];
    for (int i = threadIdx.x; i < 2048; i += 256) sW[i] = W2[i];
    __syncthreads();
    int warp = threadIdx.x >> 5, lane = threadIdx.x & 31;
    int base = (blockIdx.x * 8 + warp) * 4;
    if (base >= NN) return;
    const __half2* hin16 = sel ? g_h16B : g_h16A;
    const float2*  hin32 = (const float2*)(sel ? g_bufB : g_bufA);
    float2*        hout32 = (float2*)(sel ? g_bufA : g_bufB);
    __half2*       hout16 = sel ? g_h16A : g_h16B;
    const float*   b = g_bf[lidx];

    float accx[4], accy[4];
    float hvx[4], hvy[4];
    float dvv[4];
#pragma unroll 1
    for (int n = 0; n < 4; ++n) {
        int v = min(base + n, NN - 1);
        int r0 = g_rowptr[v], r1 = g_rowptr[v + 1];
        float ax = 0.f, ay = 0.f;
        int e = r0;
        for (; e + 4 <= r1; e += 4) {
            int u0 = __ldg(&g_col[e]);
            int u1 = __ldg(&g_col[e + 1]);
            int u2 = __ldg(&g_col[e + 2]);
            int u3 = __ldg(&g_col[e + 3]);
            float2 m0 = __half22float2(__ldg(&hin16[u0 * 32 + lane]));
            float2 m1 = __half22float2(__ldg(&hin16[u1 * 32 + lane]));
            float2 m2 = __half22float2(__ldg(&hin16[u2 * 32 + lane]));
            float2 m3 = __half22float2(__ldg(&hin16[u3 * 32 + lane]));
            ax += m0.x + m1.x + m2.x + m3.x;
            ay += m0.y + m1.y + m2.y + m3.y;
        }
        for (; e < r1; ++e) {
            int u0 = __ldg(&g_col[e]);
            float2 m0 = __half22float2(__ldg(&hin16[u0 * 32 + lane]));
            ax += m0.x;
            ay += m0.y;
        }
        float dv = g_dinv[v];
        float2 hv = hin32[v * 32 + lane];
        accx[n] = dv * (ax + dv * hv.x);
        accy[n] = dv * (ay + dv * hv.y);
        hvx[n] = hv.x; hvy[n] = hv.y;
        dvv[n] = dv;
    }

    unsigned long long o64[4];
    float fz = 0.f;
#pragma unroll
    for (int n = 0; n < 4; ++n) PACK2(o64[n], fz, fz);
#pragma unroll
    for (int k = 0; k < 32; ++k) {
        unsigned long long w0 = *(const unsigned long long*)&sW[(2 * k) * 32 + lane];
        unsigned long long w1 = *(const unsigned long long*)&sW[(2 * k + 1) * 32 + lane];
#pragma unroll
        for (int n = 0; n < 4; ++n) {
            float a  = __shfl_sync(FULL, accx[n], k);
            float bb = __shfl_sync(FULL, accy[n], k);
            unsigned long long ap, bp;
            PACK2(ap, a, a);
            PACK2(bp, bb, bb);
            FMA2(o64[n], ap, w0);
            FMA2(o64[n], bp, w1);
        }
    }
    int c = 2 * lane;
    float b0v = b[c], b1v = b[c + 1];
#pragma unroll
    for (int n = 0; n < 4; ++n) {
        int v = base + n;
        if (v >= NN) break;
        float ox, oy;
        UNPACK2(ox, oy, o64[n]);
        ox = fmaxf(ox + b0v, 0.f) + hvx[n];
        oy = fmaxf(oy + b1v, 0.f) + hvy[n];
        hout32[v * 32 + lane] = make_float2(ox, oy);
        if (write16) hout16[v * 32 + lane] = __floats2half2_rn(ox * dvv[n], oy * dvv[n]);
    }
}

// ---------------- fused pooling + MLP head (R12 exact: 1 graph/block) ----------------
__global__ void k_poolmlp(const float* __restrict__ fc1W, const float* __restrict__ fc1b,
                          const float* __restrict__ fc2W, const float* __restrict__ fc2b,
                          const float* __restrict__ fcgW, const float* __restrict__ fcgb,
                          const float* __restrict__ fcbW, const float* __restrict__ fcbb,
                          float* __restrict__ out) {
    __shared__ float2 ssum[4][32];
    __shared__ float2 smax[4][32];
    __shared__ float srow[128];
    __shared__ float s1[128];
    __shared__ float rg[64], rb[64];
    int t = threadIdx.x, warp = t >> 5, lane = t & 31;
    int g = blockIdx.x;
    int s = g_startg[g], e = g_startg[g + 1];
    const float2* h2 = (const float2*)g_bufA;
    float2 sum = make_float2(0.f, 0.f);
    float2 mx = make_float2(-1e30f, -1e30f);
    for (int v = s + warp; v < e; v += 4) {
        float2 tv = __ldg(&h2[v * 32 + lane]);
        sum.x += tv.x; sum.y += tv.y;
        mx.x = fmaxf(mx.x, tv.x); mx.y = fmaxf(mx.y, tv.y);
    }
    ssum[warp][lane] = sum;
    smax[warp][lane] = mx;
    __syncthreads();
    if (warp == 0) {
        float2 a = ssum[0][lane], b2 = ssum[1][lane], c2 = ssum[2][lane], d2 = ssum[3][lane];
        float2 ma = smax[0][lane], mb = smax[1][lane], mc = smax[2][lane], md = smax[3][lane];
        float inv = (e > s) ? 1.0f / (float)(e - s) : 0.f;
        int c = 2 * lane;
        srow[c]          = (a.x + b2.x + c2.x + d2.x) * inv;
        srow[c + 1]      = (a.y + b2.y + c2.y + d2.y) * inv;
        srow[64 + c]     = fmaxf(fmaxf(ma.x, mb.x), fmaxf(mc.x, md.x));
        srow[64 + c + 1] = fmaxf(fmaxf(ma.y, mb.y), fmaxf(mc.y, md.y));
    }
    __syncthreads();
    float acc = fc1b[t];
#pragma unroll 8
    for (int k = 0; k < 128; ++k) acc = fmaf(srow[k], __ldg(&fc1W[k * 128 + t]), acc);
    s1[t] = fmaxf(acc, 0.f);
    __syncthreads();
    if (t < 64) {
        float a = fc2b[t];
#pragma unroll 8
        for (int k = 0; k < 128; ++k) a = fmaf(s1[k], __ldg(&fc2W[k * 64 + t]), a);
        float h2v = fmaxf(a, 0.f);
        rg[t] = h2v * fcgW[t];
        rb[t] = h2v * fcbW[t];
    }
    __syncthreads();
    if (t < 32) {
        float a = rg[t] + rg[t + 32];
        float b2 = rb[t] + rb[t + 32];
#pragma unroll
        for (int o = 16; o > 0; o >>= 1) {
            a += __shfl_down_sync(FULL, a, o);
            b2 += __shfl_down_sync(FULL, b2, o);
        }
        if (t == 0) {
            out[g * 2 + 0] = a + fcgb[0];
            out[g * 2 + 1] = b2 + fcbb[0];
        }
    }
}

// ---------------- launch ----------------
extern "C" void kernel_launch(void* const* d_in, const int* in_sizes, int n_in,
                              void* d_out, int out_size) {
    const float* x    = (const float*)d_in[0];
    const void*  ei   = d_in[1];
    const void*  bat  = d_in[2];
    const float* W0   = (const float*)d_in[3];
    const float* b0   = (const float*)d_in[4];
    const float* Wh   = (const float*)d_in[5];
    const float* bh   = (const float*)d_in[6];
    const float* gam  = (const float*)d_in[7];
    const float* bet  = (const float*)d_in[8];
    const float* mea  = (const float*)d_in[9];
    const float* var  = (const float*)d_in[10];
    const float* fc1W = (const float*)d_in[11];
    const float* fc1b = (const float*)d_in[12];
    const float* fc2W = (const float*)d_in[13];
    const float* fc2b = (const float*)d_in[14];
    const float* fcgW = (const float*)d_in[15];
    const float* fcgb = (const float*)d_in[16];
    const float* fcbW = (const float*)d_in[17];
    const float* fcbb = (const float*)d_in[18];
    float* out = (float*)d_out;

    const int TB = 256;
    const int NB_NODE0 = (NN + 7) / 8;      // layer0: 1 node/warp
    const int NB_NODE  = (NN + 31) / 32;    // layers: 4 nodes/warp

    k_prep<<<2, TB>>>(ei, W0, b0, Wh, bh, gam, bet, mea, var);
    k_count_bounds<<<NB_E2 + NB_N, TB>>>(ei, bat);
    k_scan<<<SCAN_NB, 1024>>>(x);
    k_fill<<<NB_E2, TB>>>(ei);

    k_layer0<<<NB_NODE0, TB>>>();
    k_layer<<<NB_NODE, TB>>>(0, 1, 0);   // A -> B
    k_layer<<<NB_NODE, TB>>>(1, 0, 1);   // B -> A

    k_poolmlp<<<GG, 128>>>(fc1W, fc1b, fc2W, fc2b, fcgW, fcgb, fcbW, fcbb, out);
}

// round 15
// speedup vs baseline: 1.0647x; 1.0647x over previous
#include <cuda_runtime.h>
#include <cuda_fp16.h>

#define NN 100000
#define EE 1600000
#define GG 1000
#define BN_EPS 1e-5f
#define SCAN_NB 98   // ceil(NN/1024)
#define FULL 0xffffffffu

// ---------------- device scratch ----------------
__device__ int     g_is64;
__device__ int     g_cnt[NN];          // zeroed by k_scan after use
__device__ int     g_fill[NN];
__device__ int     g_rowptr[NN + 1];
__device__ int     g_col[EE];
__device__ float   g_dinv[NN];
__device__ __half2 g_xsh[NN * 2];      // x pre-scaled by dinv, packed fp16
__device__ float   g_bufA[NN * 64];
__device__ float   g_bufB[NN * 64];
__device__ __half2 g_h16A[NN * 32];    // prescaled by dinv_u
__device__ __half2 g_h16B[NN * 32];
__device__ unsigned long long g_scan_pub[SCAN_NB];
__device__ int     g_startg[GG + 1];
__device__ float   g_W0f[3 * 64];
__device__ float   g_b0f[64];
__device__ float   g_Wf[2][64 * 64];
__device__ float   g_bf[2][64];

__device__ __forceinline__ int ld_idx(const void* p, long i, int is64) {
    if (is64) return (int)((const long long*)p)[i];
    return ((const int*)p)[i];
}

#define PACK2(dst, lo, hi) asm("mov.b64 %0, {%1, %2};" : "=l"(dst) : "f"(lo), "f"(hi))
#define UNPACK2(lo, hi, src) asm("mov.b64 {%0, %1}, %2;" : "=f"(lo), "=f"(hi) : "l"(src))
#define FMA2(acc, a, b) asm("fma.rn.f32x2 %0, %1, %2, %0;" : "+l"(acc) : "l"(a), "l"(b))

// ---------------- prep (2 blocks) ----------------
__global__ void k_prep(const void* ei,
                       const float* __restrict__ W0, const float* __restrict__ b0,
                       const float* __restrict__ Wh, const float* __restrict__ bh,
                       const float* __restrict__ gam, const float* __restrict__ bet,
                       const float* __restrict__ mea, const float* __restrict__ var) {
    if (blockIdx.x == 0) {
        __shared__ int sh_any;
        if (threadIdx.x == 0) sh_any = 0;
        __syncthreads();
        long stride = EE / 256;
        long e = (long)threadIdx.x * stride + 1;
        const int* w = (const int*)ei;
        if (w[2 * e + 1] != 0) sh_any = 1;
        __syncthreads();
        if (threadIdx.x == 0) g_is64 = (sh_any == 0) ? 1 : 0;
    } else {
        for (int t = threadIdx.x; t < 3 * 64; t += 256) {
            int c = t % 64;
            g_W0f[t] = W0[t] * (gam[c] * rsqrtf(var[c] + BN_EPS));
        }
        for (int t = threadIdx.x; t < 64; t += 256) {
            float sc = gam[t] * rsqrtf(var[t] + BN_EPS);
            g_b0f[t] = (b0[t] - mea[t]) * sc + bet[t];
        }
        for (int l = 0; l < 2; ++l) {
            const float* G = gam + 64 * (l + 1);
            const float* B = bet + 64 * (l + 1);
            const float* M = mea + 64 * (l + 1);
            const float* V = var + 64 * (l + 1);
            for (int t = threadIdx.x; t < 64 * 64; t += 256) {
                int c = t % 64;
                g_Wf[l][t] = Wh[l * 4096 + t] * (G[c] * rsqrtf(V[c] + BN_EPS));
            }
            for (int t = threadIdx.x; t < 64; t += 256) {
                float sc = G[t] * rsqrtf(V[t] + BN_EPS);
                g_bf[l][t] = (bh[l * 64 + t] - M[t]) * sc + B[t];
            }
        }
    }
}

// ---------------- count + bounds ----------------
#define NB_E2 ((EE + 511) / 512)
#define NB_E1 ((EE + 255) / 256)
#define NB_N  ((NN + 255) / 256)

__global__ void k_count_bounds(const void* ei, const void* batch) {
    int is64 = g_is64;
    if (blockIdx.x < NB_E2) {
        int e = (blockIdx.x * 256 + threadIdx.x) * 2;
        if (e >= EE) return;
        int d0, d1;
        if (is64) {
            longlong2 a = *(const longlong2*)((const long long*)ei + EE + e);
            d0 = (int)a.x; d1 = (int)a.y;
        } else {
            int2 a = *(const int2*)((const int*)ei + EE + e);
            d0 = a.x; d1 = a.y;
        }
        atomicAdd(&g_cnt[d0], 1);
        atomicAdd(&g_cnt[d1], 1);
    } else {
        int v = (blockIdx.x - NB_E2) * 256 + threadIdx.x;
        if (v >= NN) return;
        int b = ld_idx(batch, v, is64);
        if (v == 0) {
            for (int g = 0; g <= b; ++g) g_startg[g] = 0;
        } else {
            int pb = ld_idx(batch, v - 1, is64);
            for (int g = pb + 1; g <= b; ++g) g_startg[g] = v;
        }
        if (v == NN - 1) {
            for (int g = b + 1; g <= GG; ++g) g_startg[g] = NN;
        }
    }
}

// ---------------- single-pass scan, warp-parallel lookback ----------------
__global__ void k_scan(const float* __restrict__ x) {
    __shared__ int swarp[32];
    __shared__ int s_prev;
    int t = threadIdx.x, b = blockIdx.x;
    int i = b * 1024 + t;
    int v = (i < NN) ? g_cnt[i] : 0;
    int lane = t & 31, w = t >> 5;

    int xx = v;
#pragma unroll
    for (int off = 1; off < 32; off <<= 1) {
        int y = __shfl_up_sync(FULL, xx, off);
        if (lane >= off) xx += y;
    }
    if (lane == 31) swarp[w] = xx;
    __syncthreads();
    if (t < 32) {
        int z = swarp[t];
#pragma unroll
        for (int off = 1; off < 32; off <<= 1) {
            int y = __shfl_up_sync(FULL, z, off);
            if (t >= off) z += y;
        }
        swarp[t] = z;
    }
    __syncthreads();
    int incl = xx + (w > 0 ? swarp[w - 1] : 0);
    int agg = swarp[31];
    __syncthreads();

    if (b == 0) {
        if (t == 0) {
            atomicExch(&g_scan_pub[0], (2ULL << 32) | (unsigned)agg);
            s_prev = 0;
        }
    } else {
        if (t == 0) atomicExch(&g_scan_pub[b], (1ULL << 32) | (unsigned)agg);
        if (t < 32) {
            int run = 0;
            int end = b;
            while (true) {
                int j = end - 32 + lane;
                unsigned long long p;
                unsigned st;
                if (j >= 0) {
                    p = atomicAdd(&g_scan_pub[j], 0ULL);
                    st = (unsigned)(p >> 32);
                } else { p = 0; st = 2u; }
                unsigned inval = __ballot_sync(FULL, st == 0u);
                if (inval) continue;
                unsigned pref = __ballot_sync(FULL, st == 2u);
                int val;
                if (pref) {
                    int hi = 31 - __clz(pref);
                    val = (lane >= hi) ? (int)(unsigned)p : 0;
                } else {
                    val = (int)(unsigned)p;
                }
#pragma unroll
                for (int o = 16; o > 0; o >>= 1) val += __shfl_xor_sync(FULL, val, o);
                run += val;
                if (pref) break;
                end -= 32;
            }
            if (lane == 0) {
                atomicExch(&g_scan_pub[b], (2ULL << 32) | (unsigned)(run + agg));
                s_prev = run;
            }
        }
    }
    __syncthreads();
    int ex = s_prev + incl - v;
    if (i < NN) {
        g_rowptr[i] = ex;
        g_fill[i] = ex;
        float dv = rsqrtf((float)v + 1.0f);
        g_dinv[i] = dv;
        g_cnt[i] = 0;
        g_xsh[i * 2 + 0] = __floats2half2_rn(x[i * 3 + 0] * dv, x[i * 3 + 1] * dv);
        g_xsh[i * 2 + 1] = __floats2half2_rn(x[i * 3 + 2] * dv, 0.f);
    }
    if (b == 0 && t == 0) g_rowptr[NN] = EE;
}

// ---------------- fill: 1 edge/thread (max TLP for latency-bound atomic+scatter) ----------------
__global__ void k_fill(const void* ei) {
    if (blockIdx.x == 0 && threadIdx.x < SCAN_NB)
        g_scan_pub[threadIdx.x] = 0ULL;
    int is64 = g_is64;
    int e = blockIdx.x * 256 + threadIdx.x;
    if (e >= EE) return;
    int s, d;
    if (is64) {
        s = (int)((const long long*)ei)[e];
        d = (int)((const long long*)ei)[EE + e];
    } else {
        s = ((const int*)ei)[e];
        d = ((const int*)ei)[EE + e];
    }
    g_col[atomicAdd(&g_fill[d], 1)] = s;
}

// ---------------- layer 0: per-lane packed fp16 xs gather (R12 exact) ----------------
__device__ __forceinline__ void xs_acc(int u, float& a0, float& a1, float& a2) {
    uint2 pk = __ldg((const uint2*)&g_xsh[u * 2]);
    __half2 p0 = *reinterpret_cast<__half2*>(&pk.x);
    __half2 p1 = *reinterpret_cast<__half2*>(&pk.y);
    float2 f0 = __half22float2(p0);
    a0 += f0.x;
    a1 += f0.y;
    a2 += __low2float(p1);
}

__global__ void k_layer0() {
    int warp = threadIdx.x >> 5, lane = threadIdx.x & 31;
    int v = blockIdx.x * 8 + warp;
    if (v >= NN) return;
    int r0 = g_rowptr[v], r1 = g_rowptr[v + 1];
    float a0 = 0.f, a1 = 0.f, a2 = 0.f;
    for (int e = r0 + lane; e < r1; e += 32) {
        int u = __ldg(&g_col[e]);
        xs_acc(u, a0, a1, a2);
    }
#pragma unroll
    for (int o = 16; o > 0; o >>= 1) {
        a0 += __shfl_xor_sync(FULL, a0, o);
        a1 += __shfl_xor_sync(FULL, a1, o);
        a2 += __shfl_xor_sync(FULL, a2, o);
    }
    float dv = g_dinv[v];
    float s0 = 0.f, s1 = 0.f, s2 = 0.f;
    xs_acc(v, s0, s1, s2);
    a0 = dv * (a0 + s0);
    a1 = dv * (a1 + s1);
    a2 = dv * (a2 + s2);
    int c = 2 * lane;
    float o0 = a0 * g_W0f[c]     + a1 * g_W0f[64 + c]     + a2 * g_W0f[128 + c]     + g_b0f[c];
    float o1 = a0 * g_W0f[c + 1] + a1 * g_W0f[64 + c + 1] + a2 * g_W0f[128 + c + 1] + g_b0f[c + 1];
    o0 = fmaxf(o0, 0.f);
    o1 = fmaxf(o1, 0.f);
    ((float2*)g_bufA)[v * 32 + lane] = make_float2(o0, o1);
    g_h16A[v * 32 + lane] = __floats2half2_rn(o0 * dv, o1 * dv);
}

// ---------------- layers 1,2: 4 nodes/warp; x4 gather ILP; shared-weight packed-FMA matmul (R12 exact) ----------------
__global__ void k_layer(int sel, int write16, int lidx) {
    __shared__ float2 sW[64 * 32];
    const float2* W2 = (const float2*)g_Wf[lidx];
    for (int i = threadIdx.x; i < 2048; i += 256) sW[i] = W2[i];
    __syncthreads();
    int warp = threadIdx.x >> 5, lane = threadIdx.x & 31;
    int base = (blockIdx.x * 8 + warp) * 4;
    if (base >= NN) return;
    const __half2* hin16 = sel ? g_h16B : g_h16A;
    const float2*  hin32 = (const float2*)(sel ? g_bufB : g_bufA);
    float2*        hout32 = (float2*)(sel ? g_bufA : g_bufB);
    __half2*       hout16 = sel ? g_h16A : g_h16B;
    const float*   b = g_bf[lidx];

    float accx[4], accy[4];
    float hvx[4], hvy[4];
    float dvv[4];
#pragma unroll 1
    for (int n = 0; n < 4; ++n) {
        int v = min(base + n, NN - 1);
        int r0 = g_rowptr[v], r1 = g_rowptr[v + 1];
        float ax = 0.f, ay = 0.f;
        int e = r0;
        for (; e + 4 <= r1; e += 4) {
            int u0 = __ldg(&g_col[e]);
            int u1 = __ldg(&g_col[e + 1]);
            int u2 = __ldg(&g_col[e + 2]);
            int u3 = __ldg(&g_col[e + 3]);
            float2 m0 = __half22float2(__ldg(&hin16[u0 * 32 + lane]));
            float2 m1 = __half22float2(__ldg(&hin16[u1 * 32 + lane]));
            float2 m2 = __half22float2(__ldg(&hin16[u2 * 32 + lane]));
            float2 m3 = __half22float2(__ldg(&hin16[u3 * 32 + lane]));
            ax += m0.x + m1.x + m2.x + m3.x;
            ay += m0.y + m1.y + m2.y + m3.y;
        }
        for (; e < r1; ++e) {
            int u0 = __ldg(&g_col[e]);
            float2 m0 = __half22float2(__ldg(&hin16[u0 * 32 + lane]));
            ax += m0.x;
            ay += m0.y;
        }
        float dv = g_dinv[v];
        float2 hv = hin32[v * 32 + lane];
        accx[n] = dv * (ax + dv * hv.x);
        accy[n] = dv * (ay + dv * hv.y);
        hvx[n] = hv.x; hvy[n] = hv.y;
        dvv[n] = dv;
    }

    unsigned long long o64[4];
    float fz = 0.f;
#pragma unroll
    for (int n = 0; n < 4; ++n) PACK2(o64[n], fz, fz);
#pragma unroll
    for (int k = 0; k < 32; ++k) {
        unsigned long long w0 = *(const unsigned long long*)&sW[(2 * k) * 32 + lane];
        unsigned long long w1 = *(const unsigned long long*)&sW[(2 * k + 1) * 32 + lane];
#pragma unroll
        for (int n = 0; n < 4; ++n) {
            float a  = __shfl_sync(FULL, accx[n], k);
            float bb = __shfl_sync(FULL, accy[n], k);
            unsigned long long ap, bp;
            PACK2(ap, a, a);
            PACK2(bp, bb, bb);
            FMA2(o64[n], ap, w0);
            FMA2(o64[n], bp, w1);
        }
    }
    int c = 2 * lane;
    float b0v = b[c], b1v = b[c + 1];
#pragma unroll
    for (int n = 0; n < 4; ++n) {
        int v = base + n;
        if (v >= NN) break;
        float ox, oy;
        UNPACK2(ox, oy, o64[n]);
        ox = fmaxf(ox + b0v, 0.f) + hvx[n];
        oy = fmaxf(oy + b1v, 0.f) + hvy[n];
        hout32[v * 32 + lane] = make_float2(ox, oy);
        if (write16) hout16[v * 32 + lane] = __floats2half2_rn(ox * dvv[n], oy * dvv[n]);
    }
}

// ---------------- fused pooling + MLP head (R12 exact: 1 graph/block) ----------------
__global__ void k_poolmlp(const float* __restrict__ fc1W, const float* __restrict__ fc1b,
                          const float* __restrict__ fc2W, const float* __restrict__ fc2b,
                          const float* __restrict__ fcgW, const float* __restrict__ fcgb,
                          const float* __restrict__ fcbW, const float* __restrict__ fcbb,
                          float* __restrict__ out) {
    __shared__ float2 ssum[4][32];
    __shared__ float2 smax[4][32];
    __shared__ float srow[128];
    __shared__ float s1[128];
    __shared__ float rg[64], rb[64];
    int t = threadIdx.x, warp = t >> 5, lane = t & 31;
    int g = blockIdx.x;
    int s = g_startg[g], e = g_startg[g + 1];
    const float2* h2 = (const float2*)g_bufA;
    float2 sum = make_float2(0.f, 0.f);
    float2 mx = make_float2(-1e30f, -1e30f);
    for (int v = s + warp; v < e; v += 4) {
        float2 tv = __ldg(&h2[v * 32 + lane]);
        sum.x += tv.x; sum.y += tv.y;
        mx.x = fmaxf(mx.x, tv.x); mx.y = fmaxf(mx.y, tv.y);
    }
    ssum[warp][lane] = sum;
    smax[warp][lane] = mx;
    __syncthreads();
    if (warp == 0) {
        float2 a = ssum[0][lane], b2 = ssum[1][lane], c2 = ssum[2][lane], d2 = ssum[3][lane];
        float2 ma = smax[0][lane], mb = smax[1][lane], mc = smax[2][lane], md = smax[3][lane];
        float inv = (e > s) ? 1.0f / (float)(e - s) : 0.f;
        int c = 2 * lane;
        srow[c]          = (a.x + b2.x + c2.x + d2.x) * inv;
        srow[c + 1]      = (a.y + b2.y + c2.y + d2.y) * inv;
        srow[64 + c]     = fmaxf(fmaxf(ma.x, mb.x), fmaxf(mc.x, md.x));
        srow[64 + c + 1] = fmaxf(fmaxf(ma.y, mb.y), fmaxf(mc.y, md.y));
    }
    __syncthreads();
    float acc = fc1b[t];
#pragma unroll 8
    for (int k = 0; k < 128; ++k) acc = fmaf(srow[k], __ldg(&fc1W[k * 128 + t]), acc);
    s1[t] = fmaxf(acc, 0.f);
    __syncthreads();
    if (t < 64) {
        float a = fc2b[t];
#pragma unroll 8
        for (int k = 0; k < 128; ++k) a = fmaf(s1[k], __ldg(&fc2W[k * 64 + t]), a);
        float h2v = fmaxf(a, 0.f);
        rg[t] = h2v * fcgW[t];
        rb[t] = h2v * fcbW[t];
    }
    __syncthreads();
    if (t < 32) {
        float a = rg[t] + rg[t + 32];
        float b2 = rb[t] + rb[t + 32];
#pragma unroll
        for (int o = 16; o > 0; o >>= 1) {
            a += __shfl_down_sync(FULL, a, o);
            b2 += __shfl_down_sync(FULL, b2, o);
        }
        if (t == 0) {
            out[g * 2 + 0] = a + fcgb[0];
            out[g * 2 + 1] = b2 + fcbb[0];
        }
    }
}

// ---------------- launch ----------------
extern "C" void kernel_launch(void* const* d_in, const int* in_sizes, int n_in,
                              void* d_out, int out_size) {
    const float* x    = (const float*)d_in[0];
    const void*  ei   = d_in[1];
    const void*  bat  = d_in[2];
    const float* W0   = (const float*)d_in[3];
    const float* b0   = (const float*)d_in[4];
    const float* Wh   = (const float*)d_in[5];
    const float* bh   = (const float*)d_in[6];
    const float* gam  = (const float*)d_in[7];
    const float* bet  = (const float*)d_in[8];
    const float* mea  = (const float*)d_in[9];
    const float* var  = (const float*)d_in[10];
    const float* fc1W = (const float*)d_in[11];
    const float* fc1b = (const float*)d_in[12];
    const float* fc2W = (const float*)d_in[13];
    const float* fc2b = (const float*)d_in[14];
    const float* fcgW = (const float*)d_in[15];
    const float* fcgb = (const float*)d_in[16];
    const float* fcbW = (const float*)d_in[17];
    const float* fcbb = (const float*)d_in[18];
    float* out = (float*)d_out;

    const int TB = 256;
    const int NB_NODE0 = (NN + 7) / 8;      // layer0: 1 node/warp
    const int NB_NODE  = (NN + 31) / 32;    // layers: 4 nodes/warp

    k_prep<<<2, TB>>>(ei, W0, b0, Wh, bh, gam, bet, mea, var);
    k_count_bounds<<<NB_E2 + NB_N, TB>>>(ei, bat);
    k_scan<<<SCAN_NB, 1024>>>(x);
    k_fill<<<NB_E1, TB>>>(ei);

    k_layer0<<<NB_NODE0, TB>>>();
    k_layer<<<NB_NODE, TB>>>(0, 1, 0);   // A -> B
    k_layer<<<NB_NODE, TB>>>(1, 0, 1);   // B -> A

    k_poolmlp<<<GG, 128>>>(fc1W, fc1b, fc2W, fc2b, fcgW, fcgb, fcbW, fcbb, out);
}

// round 16
// speedup vs baseline: 1.0872x; 1.0211x over previous
#include <cuda_runtime.h>
#include <cuda_fp16.h>

#define NN 100000
#define EE 1600000
#define GG 1000
#define BN_EPS 1e-5f
#define SCAN_NB 98   // ceil(NN/1024)
#define FULL 0xffffffffu

// ---------------- device scratch ----------------
__device__ int     g_is64;
__device__ int     g_cnt[NN];          // zeroed by k_scan after use
__device__ int     g_rank[EE];         // per-edge rank within destination row
__device__ int     g_rowptr[NN + 1];
__device__ int     g_col[EE];
__device__ float   g_dinv[NN];
__device__ __half2 g_xsh[NN * 2];      // x pre-scaled by dinv, packed fp16
__device__ float   g_bufA[NN * 64];
__device__ float   g_bufB[NN * 64];
__device__ __half2 g_h16A[NN * 32];    // prescaled by dinv_u
__device__ __half2 g_h16B[NN * 32];
__device__ unsigned long long g_scan_pub[SCAN_NB];
__device__ int     g_startg[GG + 1];
__device__ float   g_W0f[3 * 64];
__device__ float   g_b0f[64];
__device__ float   g_Wf[2][64 * 64];
__device__ float   g_bf[2][64];

__device__ __forceinline__ int ld_idx(const void* p, long i, int is64) {
    if (is64) return (int)((const long long*)p)[i];
    return ((const int*)p)[i];
}

#define PACK2(dst, lo, hi) asm("mov.b64 %0, {%1, %2};" : "=l"(dst) : "f"(lo), "f"(hi))
#define UNPACK2(lo, hi, src) asm("mov.b64 {%0, %1}, %2;" : "=f"(lo), "=f"(hi) : "l"(src))
#define FMA2(acc, a, b) asm("fma.rn.f32x2 %0, %1, %2, %0;" : "+l"(acc) : "l"(a), "l"(b))

// ---------------- prep (2 blocks) ----------------
__global__ void k_prep(const void* ei,
                       const float* __restrict__ W0, const float* __restrict__ b0,
                       const float* __restrict__ Wh, const float* __restrict__ bh,
                       const float* __restrict__ gam, const float* __restrict__ bet,
                       const float* __restrict__ mea, const float* __restrict__ var) {
    if (blockIdx.x == 0) {
        __shared__ int sh_any;
        if (threadIdx.x == 0) sh_any = 0;
        __syncthreads();
        long stride = EE / 256;
        long e = (long)threadIdx.x * stride + 1;
        const int* w = (const int*)ei;
        if (w[2 * e + 1] != 0) sh_any = 1;
        __syncthreads();
        if (threadIdx.x == 0) g_is64 = (sh_any == 0) ? 1 : 0;
    } else {
        for (int t = threadIdx.x; t < 3 * 64; t += 256) {
            int c = t % 64;
            g_W0f[t] = W0[t] * (gam[c] * rsqrtf(var[c] + BN_EPS));
        }
        for (int t = threadIdx.x; t < 64; t += 256) {
            float sc = gam[t] * rsqrtf(var[t] + BN_EPS);
            g_b0f[t] = (b0[t] - mea[t]) * sc + bet[t];
        }
        for (int l = 0; l < 2; ++l) {
            const float* G = gam + 64 * (l + 1);
            const float* B = bet + 64 * (l + 1);
            const float* M = mea + 64 * (l + 1);
            const float* V = var + 64 * (l + 1);
            for (int t = threadIdx.x; t < 64 * 64; t += 256) {
                int c = t % 64;
                g_Wf[l][t] = Wh[l * 4096 + t] * (G[c] * rsqrtf(V[c] + BN_EPS));
            }
            for (int t = threadIdx.x; t < 64; t += 256) {
                float sc = G[t] * rsqrtf(V[t] + BN_EPS);
                g_bf[l][t] = (bh[l * 64 + t] - M[t]) * sc + B[t];
            }
        }
    }
}

// ---------------- count (capturing rank) + bounds ----------------
#define NB_E2 ((EE + 511) / 512)
#define NB_N  ((NN + 255) / 256)

__global__ void k_count_bounds(const void* ei, const void* batch) {
    int is64 = g_is64;
    if (blockIdx.x < NB_E2) {
        int e = (blockIdx.x * 256 + threadIdx.x) * 2;
        if (e >= EE) return;
        int d0, d1;
        if (is64) {
            longlong2 a = *(const longlong2*)((const long long*)ei + EE + e);
            d0 = (int)a.x; d1 = (int)a.y;
        } else {
            int2 a = *(const int2*)((const int*)ei + EE + e);
            d0 = a.x; d1 = a.y;
        }
        int r0 = atomicAdd(&g_cnt[d0], 1);
        int r1 = atomicAdd(&g_cnt[d1], 1);
        g_rank[e]     = r0;
        g_rank[e + 1] = r1;
    } else {
        int v = (blockIdx.x - NB_E2) * 256 + threadIdx.x;
        if (v >= NN) return;
        int b = ld_idx(batch, v, is64);
        if (v == 0) {
            for (int g = 0; g <= b; ++g) g_startg[g] = 0;
        } else {
            int pb = ld_idx(batch, v - 1, is64);
            for (int g = pb + 1; g <= b; ++g) g_startg[g] = v;
        }
        if (v == NN - 1) {
            for (int g = b + 1; g <= GG; ++g) g_startg[g] = NN;
        }
    }
}

// ---------------- single-pass scan, warp-parallel lookback ----------------
__global__ void k_scan(const float* __restrict__ x) {
    __shared__ int swarp[32];
    __shared__ int s_prev;
    int t = threadIdx.x, b = blockIdx.x;
    int i = b * 1024 + t;
    int v = (i < NN) ? g_cnt[i] : 0;
    int lane = t & 31, w = t >> 5;

    int xx = v;
#pragma unroll
    for (int off = 1; off < 32; off <<= 1) {
        int y = __shfl_up_sync(FULL, xx, off);
        if (lane >= off) xx += y;
    }
    if (lane == 31) swarp[w] = xx;
    __syncthreads();
    if (t < 32) {
        int z = swarp[t];
#pragma unroll
        for (int off = 1; off < 32; off <<= 1) {
            int y = __shfl_up_sync(FULL, z, off);
            if (t >= off) z += y;
        }
        swarp[t] = z;
    }
    __syncthreads();
    int incl = xx + (w > 0 ? swarp[w - 1] : 0);
    int agg = swarp[31];
    __syncthreads();

    if (b == 0) {
        if (t == 0) {
            atomicExch(&g_scan_pub[0], (2ULL << 32) | (unsigned)agg);
            s_prev = 0;
        }
    } else {
        if (t == 0) atomicExch(&g_scan_pub[b], (1ULL << 32) | (unsigned)agg);
        if (t < 32) {
            int run = 0;
            int end = b;
            while (true) {
                int j = end - 32 + lane;
                unsigned long long p;
                unsigned st;
                if (j >= 0) {
                    p = atomicAdd(&g_scan_pub[j], 0ULL);
                    st = (unsigned)(p >> 32);
                } else { p = 0; st = 2u; }
                unsigned inval = __ballot_sync(FULL, st == 0u);
                if (inval) continue;
                unsigned pref = __ballot_sync(FULL, st == 2u);
                int val;
                if (pref) {
                    int hi = 31 - __clz(pref);
                    val = (lane >= hi) ? (int)(unsigned)p : 0;
                } else {
                    val = (int)(unsigned)p;
                }
#pragma unroll
                for (int o = 16; o > 0; o >>= 1) val += __shfl_xor_sync(FULL, val, o);
                run += val;
                if (pref) break;
                end -= 32;
            }
            if (lane == 0) {
                atomicExch(&g_scan_pub[b], (2ULL << 32) | (unsigned)(run + agg));
                s_prev = run;
            }
        }
    }
    __syncthreads();
    int ex = s_prev + incl - v;
    if (i < NN) {
        g_rowptr[i] = ex;
        float dv = rsqrtf((float)v + 1.0f);
        g_dinv[i] = dv;
        g_cnt[i] = 0;
        g_xsh[i * 2 + 0] = __floats2half2_rn(x[i * 3 + 0] * dv, x[i * 3 + 1] * dv);
        g_xsh[i * 2 + 1] = __floats2half2_rn(x[i * 3 + 2] * dv, 0.f);
    }
    if (b == 0 && t == 0) g_rowptr[NN] = EE;
}

// ---------------- fill: atomic-free scatter via precomputed ranks (2 edges/thread) ----------------
__global__ void k_fill(const void* ei) {
    if (blockIdx.x == 0 && threadIdx.x < SCAN_NB)
        g_scan_pub[threadIdx.x] = 0ULL;
    int is64 = g_is64;
    int e = (blockIdx.x * 256 + threadIdx.x) * 2;
    if (e >= EE) return;
    int s0, s1, d0, d1;
    if (is64) {
        longlong2 sa = *(const longlong2*)((const long long*)ei + e);
        longlong2 da = *(const longlong2*)((const long long*)ei + EE + e);
        s0 = (int)sa.x; s1 = (int)sa.y;
        d0 = (int)da.x; d1 = (int)da.y;
    } else {
        int2 sa = *(const int2*)((const int*)ei + e);
        int2 da = *(const int2*)((const int*)ei + EE + e);
        s0 = sa.x; s1 = sa.y;
        d0 = da.x; d1 = da.y;
    }
    int2 rk = *(const int2*)&g_rank[e];
    g_col[g_rowptr[d0] + rk.x] = s0;
    g_col[g_rowptr[d1] + rk.y] = s1;
}

// ---------------- layer 0: per-lane packed fp16 xs gather (R12 exact) ----------------
__device__ __forceinline__ void xs_acc(int u, float& a0, float& a1, float& a2) {
    uint2 pk = __ldg((const uint2*)&g_xsh[u * 2]);
    __half2 p0 = *reinterpret_cast<__half2*>(&pk.x);
    __half2 p1 = *reinterpret_cast<__half2*>(&pk.y);
    float2 f0 = __half22float2(p0);
    a0 += f0.x;
    a1 += f0.y;
    a2 += __low2float(p1);
}

__global__ void k_layer0() {
    int warp = threadIdx.x >> 5, lane = threadIdx.x & 31;
    int v = blockIdx.x * 8 + warp;
    if (v >= NN) return;
    int r0 = g_rowptr[v], r1 = g_rowptr[v + 1];
    float a0 = 0.f, a1 = 0.f, a2 = 0.f;
    for (int e = r0 + lane; e < r1; e += 32) {
        int u = __ldg(&g_col[e]);
        xs_acc(u, a0, a1, a2);
    }
#pragma unroll
    for (int o = 16; o > 0; o >>= 1) {
        a0 += __shfl_xor_sync(FULL, a0, o);
        a1 += __shfl_xor_sync(FULL, a1, o);
        a2 += __shfl_xor_sync(FULL, a2, o);
    }
    float dv = g_dinv[v];
    float s0 = 0.f, s1 = 0.f, s2 = 0.f;
    xs_acc(v, s0, s1, s2);
    a0 = dv * (a0 + s0);
    a1 = dv * (a1 + s1);
    a2 = dv * (a2 + s2);
    int c = 2 * lane;
    float o0 = a0 * g_W0f[c]     + a1 * g_W0f[64 + c]     + a2 * g_W0f[128 + c]     + g_b0f[c];
    float o1 = a0 * g_W0f[c + 1] + a1 * g_W0f[64 + c + 1] + a2 * g_W0f[128 + c + 1] + g_b0f[c + 1];
    o0 = fmaxf(o0, 0.f);
    o1 = fmaxf(o1, 0.f);
    ((float2*)g_bufA)[v * 32 + lane] = make_float2(o0, o1);
    g_h16A[v * 32 + lane] = __floats2half2_rn(o0 * dv, o1 * dv);
}

// ---------------- layers 1,2: 4 nodes/warp; x4 gather ILP; shared-weight packed-FMA matmul (R12 exact) ----------------
__global__ void k_layer(int sel, int write16, int lidx) {
    __shared__ float2 sW[64 * 32];
    const float2* W2 = (const float2*)g_Wf[lidx];
    for (int i = threadIdx.x; i < 2048; i += 256) sW[i] = W2[i];
    __syncthreads();
    int warp = threadIdx.x >> 5, lane = threadIdx.x & 31;
    int base = (blockIdx.x * 8 + warp) * 4;
    if (base >= NN) return;
    const __half2* hin16 = sel ? g_h16B : g_h16A;
    const float2*  hin32 = (const float2*)(sel ? g_bufB : g_bufA);
    float2*        hout32 = (float2*)(sel ? g_bufA : g_bufB);
    __half2*       hout16 = sel ? g_h16A : g_h16B;
    const float*   b = g_bf[lidx];

    float accx[4], accy[4];
    float hvx[4], hvy[4];
    float dvv[4];
#pragma unroll 1
    for (int n = 0; n < 4; ++n) {
        int v = min(base + n, NN - 1);
        int r0 = g_rowptr[v], r1 = g_rowptr[v + 1];
        float ax = 0.f, ay = 0.f;
        int e = r0;
        for (; e + 4 <= r1; e += 4) {
            int u0 = __ldg(&g_col[e]);
            int u1 = __ldg(&g_col[e + 1]);
            int u2 = __ldg(&g_col[e + 2]);
            int u3 = __ldg(&g_col[e + 3]);
            float2 m0 = __half22float2(__ldg(&hin16[u0 * 32 + lane]));
            float2 m1 = __half22float2(__ldg(&hin16[u1 * 32 + lane]));
            float2 m2 = __half22float2(__ldg(&hin16[u2 * 32 + lane]));
            float2 m3 = __half22float2(__ldg(&hin16[u3 * 32 + lane]));
            ax += m0.x + m1.x + m2.x + m3.x;
            ay += m0.y + m1.y + m2.y + m3.y;
        }
        for (; e < r1; ++e) {
            int u0 = __ldg(&g_col[e]);
            float2 m0 = __half22float2(__ldg(&hin16[u0 * 32 + lane]));
            ax += m0.x;
            ay += m0.y;
        }
        float dv = g_dinv[v];
        float2 hv = hin32[v * 32 + lane];
        accx[n] = dv * (ax + dv * hv.x);
        accy[n] = dv * (ay + dv * hv.y);
        hvx[n] = hv.x; hvy[n] = hv.y;
        dvv[n] = dv;
    }

    unsigned long long o64[4];
    float fz = 0.f;
#pragma unroll
    for (int n = 0; n < 4; ++n) PACK2(o64[n], fz, fz);
#pragma unroll
    for (int k = 0; k < 32; ++k) {
        unsigned long long w0 = *(const unsigned long long*)&sW[(2 * k) * 32 + lane];
        unsigned long long w1 = *(const unsigned long long*)&sW[(2 * k + 1) * 32 + lane];
#pragma unroll
        for (int n = 0; n < 4; ++n) {
            float a  = __shfl_sync(FULL, accx[n], k);
            float bb = __shfl_sync(FULL, accy[n], k);
            unsigned long long ap, bp;
            PACK2(ap, a, a);
            PACK2(bp, bb, bb);
            FMA2(o64[n], ap, w0);
            FMA2(o64[n], bp, w1);
        }
    }
    int c = 2 * lane;
    float b0v = b[c], b1v = b[c + 1];
#pragma unroll
    for (int n = 0; n < 4; ++n) {
        int v = base + n;
        if (v >= NN) break;
        float ox, oy;
        UNPACK2(ox, oy, o64[n]);
        ox = fmaxf(ox + b0v, 0.f) + hvx[n];
        oy = fmaxf(oy + b1v, 0.f) + hvy[n];
        hout32[v * 32 + lane] = make_float2(ox, oy);
        if (write16) hout16[v * 32 + lane] = __floats2half2_rn(ox * dvv[n], oy * dvv[n]);
    }
}

// ---------------- fused pooling + MLP head (R12 exact: 1 graph/block) ----------------
__global__ void k_poolmlp(const float* __restrict__ fc1W, const float* __restrict__ fc1b,
                          const float* __restrict__ fc2W, const float* __restrict__ fc2b,
                          const float* __restrict__ fcgW, const float* __restrict__ fcgb,
                          const float* __restrict__ fcbW, const float* __restrict__ fcbb,
                          float* __restrict__ out) {
    __shared__ float2 ssum[4][32];
    __shared__ float2 smax[4][32];
    __shared__ float srow[128];
    __shared__ float s1[128];
    __shared__ float rg[64], rb[64];
    int t = threadIdx.x, warp = t >> 5, lane = t & 31;
    int g = blockIdx.x;
    int s = g_startg[g], e = g_startg[g + 1];
    const float2* h2 = (const float2*)g_bufA;
    float2 sum = make_float2(0.f, 0.f);
    float2 mx = make_float2(-1e30f, -1e30f);
    for (int v = s + warp; v < e; v += 4) {
        float2 tv = __ldg(&h2[v * 32 + lane]);
        sum.x += tv.x; sum.y += tv.y;
        mx.x = fmaxf(mx.x, tv.x); mx.y = fmaxf(mx.y, tv.y);
    }
    ssum[warp][lane] = sum;
    smax[warp][lane] = mx;
    __syncthreads();
    if (warp == 0) {
        float2 a = ssum[0][lane], b2 = ssum[1][lane], c2 = ssum[2][lane], d2 = ssum[3][lane];
        float2 ma = smax[0][lane], mb = smax[1][lane], mc = smax[2][lane], md = smax[3][lane];
        float inv = (e > s) ? 1.0f / (float)(e - s) : 0.f;
        int c = 2 * lane;
        srow[c]          = (a.x + b2.x + c2.x + d2.x) * inv;
        srow[c + 1]      = (a.y + b2.y + c2.y + d2.y) * inv;
        srow[64 + c]     = fmaxf(fmaxf(ma.x, mb.x), fmaxf(mc.x, md.x));
        srow[64 + c + 1] = fmaxf(fmaxf(ma.y, mb.y), fmaxf(mc.y, md.y));
    }
    __syncthreads();
    float acc = fc1b[t];
#pragma unroll 8
    for (int k = 0; k < 128; ++k) acc = fmaf(srow[k], __ldg(&fc1W[k * 128 + t]), acc);
    s1[t] = fmaxf(acc, 0.f);
    __syncthreads();
    if (t < 64) {
        float a = fc2b[t];
#pragma unroll 8
        for (int k = 0; k < 128; ++k) a = fmaf(s1[k], __ldg(&fc2W[k * 64 + t]), a);
        float h2v = fmaxf(a, 0.f);
        rg[t] = h2v * fcgW[t];
        rb[t] = h2v * fcbW[t];
    }
    __syncthreads();
    if (t < 32) {
        float a = rg[t] + rg[t + 32];
        float b2 = rb[t] + rb[t + 32];
#pragma unroll
        for (int o = 16; o > 0; o >>= 1) {
            a += __shfl_down_sync(FULL, a, o);
            b2 += __shfl_down_sync(FULL, b2, o);
        }
        if (t == 0) {
            out[g * 2 + 0] = a + fcgb[0];
            out[g * 2 + 1] = b2 + fcbb[0];
        }
    }
}

// ---------------- launch ----------------
extern "C" void kernel_launch(void* const* d_in, const int* in_sizes, int n_in,
                              void* d_out, int out_size) {
    const float* x    = (const float*)d_in[0];
    const void*  ei   = d_in[1];
    const void*  bat  = d_in[2];
    const float* W0   = (const float*)d_in[3];
    const float* b0   = (const float*)d_in[4];
    const float* Wh   = (const float*)d_in[5];
    const float* bh   = (const float*)d_in[6];
    const float* gam  = (const float*)d_in[7];
    const float* bet  = (const float*)d_in[8];
    const float* mea  = (const float*)d_in[9];
    const float* var  = (const float*)d_in[10];
    const float* fc1W = (const float*)d_in[11];
    const float* fc1b = (const float*)d_in[12];
    const float* fc2W = (const float*)d_in[13];
    const float* fc2b = (const float*)d_in[14];
    const float* fcgW = (const float*)d_in[15];
    const float* fcgb = (const float*)d_in[16];
    const float* fcbW = (const float*)d_in[17];
    const float* fcbb = (const float*)d_in[18];
    float* out = (float*)d_out;

    const int TB = 256;
    const int NB_NODE0 = (NN + 7) / 8;      // layer0: 1 node/warp
    const int NB_NODE  = (NN + 31) / 32;    // layers: 4 nodes/warp

    k_prep<<<2, TB>>>(ei, W0, b0, Wh, bh, gam, bet, mea, var);
    k_count_bounds<<<NB_E2 + NB_N, TB>>>(ei, bat);
    k_scan<<<SCAN_NB, 1024>>>(x);
    k_fill<<<NB_E2, TB>>>(ei);

    k_layer0<<<NB_NODE0, TB>>>();
    k_layer<<<NB_NODE, TB>>>(0, 1, 0);   // A -> B
    k_layer<<<NB_NODE, TB>>>(1, 0, 1);   // B -> A

    k_poolmlp<<<GG, 128>>>(fc1W, fc1b, fc2W, fc2b, fcgW, fcgb, fcbW, fcbb, out);
}